// round 6
// baseline (speedup 1.0000x reference)
#include <cuda_runtime.h>

// Operator3D: bs=4, v=8192, n=20, SUPPORT=4, KERNEL=32  (S*K = 128)
// inputs: [0] neighbor_index int32 (bs,v,n)
//         [1] vertices       f32   (bs,v,3)
//         [2] weights        f32   (1,1,4,32)
//         [3] displacement   f32   (3,128)
// output: feature f32 (bs,v,32)
//
// One warp per GROUP of 4 consecutive rows. Gather for all 4 rows is batched:
// 80 neighbor items spread over all 32 lanes (coalesced idx loads, MLP~9),
// staged as float4 in smem; then 4 rows of the proven scalar FFMA/FMNMX
// compute loop run back-to-back. Exposed gather latency: 2 per warp instead
// of 8 (and the 2nd has its idx prefetched). 4096 warps x exactly 2 groups.

#define BS_   4
#define V_    8192
#define N_    20
#define K_    32
#define SK_   128
#define ROWS_ (BS_ * V_)

#define GR_      4                     // rows per group
#define GITEMS_  (GR_ * N_)            // 80 gather items per group
#define GROUPS_  (ROWS_ / GR_)         // 8192

#define WPB      8
#define THREADS_ (WPB * 32)
#define BLOCKS_  512
#define NWARPS_  (BLOCKS_ * WPB)       // 4096 -> exactly 2 groups per warp

__global__ __launch_bounds__(THREADS_, 4)   // cap regs at 64: all blocks resident
void op3d_kernel(const int*   __restrict__ nb,
                 const float* __restrict__ verts,
                 const float* __restrict__ weights,
                 const float* __restrict__ disp,
                 float*       __restrict__ out)
{
    __shared__ float4 sd[WPB][GITEMS_];

    const int warp  = threadIdx.x >> 5;
    const int lane  = threadIdx.x & 31;
    const int gwarp = blockIdx.x * WPB + warp;

    // Per-lane constants: displacement columns for k = s*32 + lane, s=0..3.
    const float d00 = disp[0 * SK_ +  0 + lane];
    const float d01 = disp[0 * SK_ + 32 + lane];
    const float d02 = disp[0 * SK_ + 64 + lane];
    const float d03 = disp[0 * SK_ + 96 + lane];
    const float d10 = disp[1 * SK_ +  0 + lane];
    const float d11 = disp[1 * SK_ + 32 + lane];
    const float d12 = disp[1 * SK_ + 64 + lane];
    const float d13 = disp[1 * SK_ + 96 + lane];
    const float d20 = disp[2 * SK_ +  0 + lane];
    const float d21 = disp[2 * SK_ + 32 + lane];
    const float d22 = disp[2 * SK_ + 64 + lane];
    const float d23 = disp[2 * SK_ + 96 + lane];
    const float w0  = weights[ 0 + lane];
    const float w1  = weights[32 + lane];
    const float w2  = weights[64 + lane];
    const float w3  = weights[96 + lane];

    int g = gwarp;

    // prologue: indices for the first group (3 coalesced LDGs)
    int i0 = 0, i1 = 0, i2 = 0;
    {
        const int gb = g * GITEMS_;          // nb is flat (rows*N_)
        i0 = nb[gb + lane];
        i1 = nb[gb + 32 + lane];
        if (lane < GITEMS_ - 64) i2 = nb[gb + 64 + lane];
    }

    while (g < GROUPS_) {
        const int r0    = g * GR_;
        const int vbase = (r0 >> 13) * (V_ * 3);   // groups never span batches

        // batched gather: item = row*N_ + j, row = item/20
        #define GATHER_(ITEM, IDX) do {                                   \
            const int   _it  = (ITEM);                                    \
            const int   _row = (int)((unsigned)_it / 20u);                \
            const float* _p  = verts + vbase + (IDX) * 3;                 \
            const float* _q  = verts + (r0 + _row) * 3;                   \
            sd[warp][_it] = make_float4(_p[0]-_q[0], _p[1]-_q[1],         \
                                        _p[2]-_q[2], 0.0f);               \
        } while (0)

        GATHER_(lane,      i0);
        GATHER_(lane + 32, i1);
        if (lane < GITEMS_ - 64) GATHER_(lane + 64, i2);
        #undef GATHER_

        // prefetch next group's indices before the long compute phase
        const int gn = g + NWARPS_;
        if (gn < GROUPS_) {
            const int gbn = gn * GITEMS_;
            i0 = nb[gbn + lane];
            i1 = nb[gbn + 32 + lane];
            if (lane < GITEMS_ - 64) i2 = nb[gbn + 64 + lane];
        }

        __syncwarp();

        // compute: 4 rows back-to-back; max seeded at 0 == relu(max_n theta)
        #pragma unroll 1
        for (int row = 0; row < GR_; row++) {
            float m0 = 0.0f, m1 = 0.0f, m2 = 0.0f, m3 = 0.0f;
            const float4* sr = &sd[warp][row * N_];
            #pragma unroll
            for (int j = 0; j < N_; j++) {
                const float4 d = sr[j];
                float t0 = fmaf(d.x, d00, fmaf(d.y, d10, d.z * d20));
                float t1 = fmaf(d.x, d01, fmaf(d.y, d11, d.z * d21));
                float t2 = fmaf(d.x, d02, fmaf(d.y, d12, d.z * d22));
                float t3 = fmaf(d.x, d03, fmaf(d.y, d13, d.z * d23));
                m0 = fmaxf(m0, t0);
                m1 = fmaxf(m1, t1);
                m2 = fmaxf(m2, t2);
                m3 = fmaxf(m3, t3);
            }
            out[(r0 + row) * K_ + lane] =
                fmaf(m0, w0, fmaf(m1, w1, fmaf(m2, w2, m3 * w3)));
        }

        g = gn;
        __syncwarp();   // protect smem before next group's stores
    }
}

extern "C" void kernel_launch(void* const* d_in, const int* in_sizes, int n_in,
                              void* d_out, int out_size)
{
    const int*   nb      = (const int*)  d_in[0];
    const float* verts   = (const float*)d_in[1];
    const float* weights = (const float*)d_in[2];
    const float* disp    = (const float*)d_in[3];
    float*       out     = (float*)      d_out;

    op3d_kernel<<<BLOCKS_, THREADS_>>>(nb, verts, weights, disp, out);
}

// round 7
// speedup vs baseline: 1.0259x; 1.0259x over previous
#include <cuda_runtime.h>

// Operator3D: bs=4, v=8192, n=20, SUPPORT=4, KERNEL=32  (S*K = 128)
// inputs: [0] neighbor_index int32 (bs,v,n)
//         [1] vertices       f32   (bs,v,3)
//         [2] weights        f32   (1,1,4,32)
//         [3] displacement   f32   (3,128)
// output: feature f32 (bs,v,32)
//
// One warp per GROUP of 2 consecutive rows, grid-stride. Gather for both rows
// batched across all 32 lanes (40 items: every lane one, lanes 0-7 a second),
// staged as float4 in smem; then 2 rows of the proven scalar FFMA/FMNMX loop.
// Next group's indices are prefetched BEFORE the vert-dependent stores so the
// gather chain pipelines across groups. Grid = 740 = 5 blocks/SM * 148 SMs
// (one exact full wave at <=50 regs); 16384 groups / 5920 warps = 2.77 (~8%
// imbalance only).

#define BS_   4
#define V_    8192
#define N_    20
#define K_    32
#define SK_   128
#define ROWS_ (BS_ * V_)

#define GR_      2
#define GITEMS_  (GR_ * N_)            // 40
#define GROUPS_  (ROWS_ / GR_)         // 16384

#define WPB      8
#define THREADS_ (WPB * 32)
#define BLOCKS_  740                   // 5 blocks/SM * 148 -> one full wave
#define NWARPS_  (BLOCKS_ * WPB)       // 5920

__global__ __launch_bounds__(THREADS_, 5)   // force regs <= ~50: 5 blocks/SM
void op3d_kernel(const int*   __restrict__ nb,
                 const float* __restrict__ verts,
                 const float* __restrict__ weights,
                 const float* __restrict__ disp,
                 float*       __restrict__ out)
{
    __shared__ float4 sd[WPB][GITEMS_];

    const int warp  = threadIdx.x >> 5;
    const int lane  = threadIdx.x & 31;
    const int gwarp = blockIdx.x * WPB + warp;

    // Per-lane constants: displacement columns for k = s*32 + lane, s=0..3.
    const float d00 = disp[0 * SK_ +  0 + lane];
    const float d01 = disp[0 * SK_ + 32 + lane];
    const float d02 = disp[0 * SK_ + 64 + lane];
    const float d03 = disp[0 * SK_ + 96 + lane];
    const float d10 = disp[1 * SK_ +  0 + lane];
    const float d11 = disp[1 * SK_ + 32 + lane];
    const float d12 = disp[1 * SK_ + 64 + lane];
    const float d13 = disp[1 * SK_ + 96 + lane];
    const float d20 = disp[2 * SK_ +  0 + lane];
    const float d21 = disp[2 * SK_ + 32 + lane];
    const float d22 = disp[2 * SK_ + 64 + lane];
    const float d23 = disp[2 * SK_ + 96 + lane];
    const float w0  = weights[ 0 + lane];
    const float w1  = weights[32 + lane];
    const float w2  = weights[64 + lane];
    const float w3  = weights[96 + lane];

    // gather item mapping: item in [0,40), row = item>=20, j = item%20
    const bool hasExtra = (lane < GITEMS_ - 32);   // lanes 0..7

    int g = gwarp;

    // prologue: first group's indices (2 coalesced LDGs)
    int i0 = 0, i1 = 0;
    if (g < GROUPS_) {
        const int gb = g * GITEMS_;
        i0 = nb[gb + lane];
        if (hasExtra) i1 = nb[gb + 32 + lane];
    }

    while (g < GROUPS_) {
        const int r0    = g * GR_;
        const int vbase = (r0 >> 13) * (V_ * 3);   // groups never span batches

        // 1) prefetch next group's indices FIRST (independent LDGs in flight)
        const int gn = g + NWARPS_;
        int n0 = 0, n1 = 0;
        if (gn < GROUPS_) {
            const int gbn = gn * GITEMS_;
            n0 = nb[gbn + lane];
            if (hasExtra) n1 = nb[gbn + 32 + lane];
        }

        // 2) batched gather for current group (idx already resident)
        {
            const int   row0 = (lane >= N_);           // item = lane
            const float* p0  = verts + vbase + i0 * 3;
            const float* q0  = verts + (r0 + row0) * 3;
            sd[warp][lane] = make_float4(p0[0]-q0[0], p0[1]-q0[1],
                                         p0[2]-q0[2], 0.0f);
            if (hasExtra) {                            // item = lane+32, row 1
                const float* p1 = verts + vbase + i1 * 3;
                const float* q1 = verts + (r0 + 1) * 3;
                sd[warp][lane + 32] = make_float4(p1[0]-q1[0], p1[1]-q1[1],
                                                  p1[2]-q1[2], 0.0f);
            }
        }
        __syncwarp();

        // 3) compute: 2 rows back-to-back; max seeded at 0 == relu(max_n)
        #pragma unroll 1
        for (int row = 0; row < GR_; row++) {
            float m0 = 0.0f, m1 = 0.0f, m2 = 0.0f, m3 = 0.0f;
            const float4* sr = &sd[warp][row * N_];
            #pragma unroll
            for (int j = 0; j < N_; j++) {
                const float4 d = sr[j];
                float t0 = fmaf(d.x, d00, fmaf(d.y, d10, d.z * d20));
                float t1 = fmaf(d.x, d01, fmaf(d.y, d11, d.z * d21));
                float t2 = fmaf(d.x, d02, fmaf(d.y, d12, d.z * d22));
                float t3 = fmaf(d.x, d03, fmaf(d.y, d13, d.z * d23));
                m0 = fmaxf(m0, t0);
                m1 = fmaxf(m1, t1);
                m2 = fmaxf(m2, t2);
                m3 = fmaxf(m3, t3);
            }
            out[(r0 + row) * K_ + lane] =
                fmaf(m0, w0, fmaf(m1, w1, fmaf(m2, w2, m3 * w3)));
        }

        g  = gn;
        i0 = n0;
        i1 = n1;
        __syncwarp();   // protect smem before next group's stores
    }
}

extern "C" void kernel_launch(void* const* d_in, const int* in_sizes, int n_in,
                              void* d_out, int out_size)
{
    const int*   nb      = (const int*)  d_in[0];
    const float* verts   = (const float*)d_in[1];
    const float* weights = (const float*)d_in[2];
    const float* disp    = (const float*)d_in[3];
    float*       out     = (float*)      d_out;

    op3d_kernel<<<BLOCKS_, THREADS_>>>(nb, verts, weights, disp, out);
}